// round 10
// baseline (speedup 1.0000x reference)
#include <cuda_runtime.h>
#include <cuda_bf16.h>
#include <math.h>

typedef unsigned long long ull;

// Problem constants
#define BT   256
#define TT   250
#define II   700
#define HH   128
#define OO   20
#define B_J0 0.01f
#define BETA 1.8f

// Output layout: output[256*20], s1[256*128], s2[256*128], A_norm[1]
#define OUT_OFF_ACC  0
#define OUT_OFF_S1   (BT*OO)
#define OUT_OFF_S2   (OUT_OFF_S1 + BT*HH)
#define OUT_OFF_NORM (OUT_OFF_S2 + BT*HH)

// Static device scratch (no allocations allowed)
__device__ float g_xin[TT * BT * HH];   // 32 MB
__device__ float g_om[TT * BT * OO];    // 5.12 MB
__device__ float g_npart[64];

// ---------------------------------------------------------------------------
// f32x2 helpers
// ---------------------------------------------------------------------------
__device__ __forceinline__ ull ffma2(ull a, ull b, ull c)
{
    ull d;
    asm("fma.rn.f32x2 %0, %1, %2, %3;" : "=l"(d) : "l"(a), "l"(b), "l"(c));
    return d;
}
__device__ __forceinline__ ull add2(ull a, ull b)
{
    ull d;
    asm("add.rn.f32x2 %0, %1, %2;" : "=l"(d) : "l"(a), "l"(b));
    return d;
}
__device__ __forceinline__ ull pack2(float lo, float hi)
{
    ull d;
    asm("mov.b64 %0, {%1, %2};" : "=l"(d) : "f"(lo), "f"(hi));
    return d;
}
__device__ __forceinline__ float2 unpack2(ull v)
{
    float lo, hi;
    asm("mov.b64 {%0, %1}, %2;" : "=f"(lo), "=f"(hi) : "l"(v));
    return make_float2(lo, hi);
}

// ---------------------------------------------------------------------------
// Kernel 1: xin GEMM (unchanged from R9: 128x128 tile, FFMA2, bit-exact)
// ---------------------------------------------------------------------------
#define GTM 128
#define KT  8
#define NKTILE ((II + KT - 1) / KT)   // 88

__global__ __launch_bounds__(256, 2) void gemm_xin_kernel(
    const float* __restrict__ x,
    const float* __restrict__ w,
    const float* __restrict__ bias,
    float* __restrict__ xin)
{
    __shared__ float As[2][KT][GTM];
    __shared__ float Bs[2][KT][HH];

    const int tid = threadIdx.x;
    const int tx = tid & 15;
    const int ty = tid >> 4;
    const int bm = blockIdx.x * GTM;
    const int n0 = tx * 8;
    const int m0 = ty * 8;

    ull acc[4][8];
#pragma unroll
    for (int p = 0; p < 4; p++)
#pragma unroll
        for (int j = 0; j < 8; j++) acc[p][j] = 0ull;

    const int la_m = tid & 127;
    const int la_k = (tid >> 7) * 4;
    const float* xrow = x + (size_t)(bm + la_m) * II + la_k;
    const int bk = tid >> 5;
    const int bn = (tid & 31) * 4;

    {
        float4 av = *(const float4*)(xrow);
        float4 bv = *(const float4*)(w + (size_t)bk * HH + bn);
        As[0][la_k + 0][la_m] = av.x;
        As[0][la_k + 1][la_m] = av.y;
        As[0][la_k + 2][la_m] = av.z;
        As[0][la_k + 3][la_m] = av.w;
        *(float4*)&Bs[0][bk][bn] = bv;
    }
    __syncthreads();

    for (int tI = 0; tI < NKTILE; tI++) {
        const int buf = tI & 1;
        float4 nav, nbv;
        const bool has = (tI + 1 < NKTILE);
        if (has) {
            int k0 = (tI + 1) * KT;
            nav = (k0 + la_k + 3 < II) ? *(const float4*)(xrow + k0)
                                       : make_float4(0.f, 0.f, 0.f, 0.f);
            int kk = k0 + bk;
            nbv = (kk < II) ? *(const float4*)(w + (size_t)kk * HH + bn)
                            : make_float4(0.f, 0.f, 0.f, 0.f);
        }

#pragma unroll
        for (int k = 0; k < KT; k++) {
            ull a[4];
            const ulonglong2* Ap = (const ulonglong2*)&As[buf][k][m0];
            ulonglong2 av;
            av = Ap[0]; a[0] = av.x; a[1] = av.y;
            av = Ap[1]; a[2] = av.x; a[3] = av.y;
            float4 b0 = *(const float4*)&Bs[buf][k][n0];
            float4 b1 = *(const float4*)&Bs[buf][k][n0 + 4];
            float bj[8] = {b0.x, b0.y, b0.z, b0.w, b1.x, b1.y, b1.z, b1.w};
#pragma unroll
            for (int j = 0; j < 8; j++) {
                ull bb = pack2(bj[j], bj[j]);
#pragma unroll
                for (int p = 0; p < 4; p++)
                    acc[p][j] = ffma2(a[p], bb, acc[p][j]);
            }
        }

        if (has) {
            int nb = buf ^ 1;
            As[nb][la_k + 0][la_m] = nav.x;
            As[nb][la_k + 1][la_m] = nav.y;
            As[nb][la_k + 2][la_m] = nav.z;
            As[nb][la_k + 3][la_m] = nav.w;
            *(float4*)&Bs[nb][bk][bn] = nbv;
        }
        __syncthreads();
    }

    float bn8[8];
#pragma unroll
    for (int j = 0; j < 8; j++) bn8[j] = bias[n0 + j];

#pragma unroll
    for (int p = 0; p < 4; p++) {
        float lo[8], hi[8];
#pragma unroll
        for (int j = 0; j < 8; j++) {
            float2 v = unpack2(acc[p][j]);
            lo[j] = v.x; hi[j] = v.y;
        }
        int mg = bm + m0 + 2 * p;
#pragma unroll
        for (int half = 0; half < 2; half++) {
            const float* vv = half ? hi : lo;
            int m = mg + half;
            int bb = m / TT;
            int tt = m - bb * TT;
            float* op = xin + ((size_t)tt * BT + bb) * HH + n0;
            float4 v0, v1;
            v0.x = __fadd_rn(vv[0], bn8[0]);
            v0.y = __fadd_rn(vv[1], bn8[1]);
            v0.z = __fadd_rn(vv[2], bn8[2]);
            v0.w = __fadd_rn(vv[3], bn8[3]);
            v1.x = __fadd_rn(vv[4], bn8[4]);
            v1.y = __fadd_rn(vv[5], bn8[5]);
            v1.z = __fadd_rn(vv[6], bn8[6]);
            v1.w = __fadd_rn(vv[7], bn8[7]);
            *(float4*)(op)     = v0;
            *(float4*)(op + 4) = v1;
        }
    }
}

// ---------------------------------------------------------------------------
// Paired dual gather: one ascending 4-padded list; two matrices; each thread
// carries an (h, h+1) f32x2 pair per matrix. Each lane of add.rn.f32x2 is an
// independent IEEE fp32 add in ascending row order -> bit-identical per
// column chain. Pad index 128 hits appended zero rows (q + 0.0f exact).
// ---------------------------------------------------------------------------
template<int SB>
__device__ __forceinline__ void dual_gather2(const float* __restrict__ wa,
                                             const float* __restrict__ wb,
                                             const int* __restrict__ lst,
                                             int cpad, int ea, int eb,
                                             ull& qa, ull& qb)
{
    ull A = 0ull, B = 0ull;
    int nb = cpad >> 2;
    if (nb) {
        const int4* L = (const int4*)lst;
        int4 id = L[0];
        ull a0 = *(const ull*)(wa + (id.x << 7) + ea);
        ull a1 = *(const ull*)(wa + (id.y << 7) + ea);
        ull a2 = *(const ull*)(wa + (id.z << 7) + ea);
        ull a3 = *(const ull*)(wa + (id.w << 7) + ea);
        ull b0 = *(const ull*)(wb + id.x * SB + eb);
        ull b1 = *(const ull*)(wb + id.y * SB + eb);
        ull b2 = *(const ull*)(wb + id.z * SB + eb);
        ull b3 = *(const ull*)(wb + id.w * SB + eb);
        for (int i = 1; i < nb; i++) {
            int4 idn = L[i];
            ull na0 = *(const ull*)(wa + (idn.x << 7) + ea);
            ull na1 = *(const ull*)(wa + (idn.y << 7) + ea);
            ull na2 = *(const ull*)(wa + (idn.z << 7) + ea);
            ull na3 = *(const ull*)(wa + (idn.w << 7) + ea);
            ull nb0 = *(const ull*)(wb + idn.x * SB + eb);
            ull nb1 = *(const ull*)(wb + idn.y * SB + eb);
            ull nb2 = *(const ull*)(wb + idn.z * SB + eb);
            ull nb3 = *(const ull*)(wb + idn.w * SB + eb);
            A = add2(A, a0); B = add2(B, b0);
            A = add2(A, a1); B = add2(B, b1);
            A = add2(A, a2); B = add2(B, b2);
            A = add2(A, a3); B = add2(B, b3);
            a0 = na0; a1 = na1; a2 = na2; a3 = na3;
            b0 = nb0; b1 = nb1; b2 = nb2; b3 = nb3;
        }
        A = add2(A, a0); B = add2(B, b0);
        A = add2(A, a1); B = add2(B, b1);
        A = add2(A, a2); B = add2(B, b2);
        A = add2(A, a3); B = add2(B, b3);
    }
    qa = A; qb = B;
}

__device__ __forceinline__ float decay(float tau)
{
    float u = __fdiv_rn(-1.0f, tau);
    return (float)exp((double)u);
}

// ---------------------------------------------------------------------------
// Kernel 2: the scan. 128 CTAs x 128 threads; row r = tid>>6 (2 warps/row,
// one warp per SMSP pairwise). Thread l = tid&63 owns h = {2l, 2l+1}.
// Named 64-thread barriers per row; hoisted dual gathers (R9 structure).
// ---------------------------------------------------------------------------
#define WROW 129
#define SCAN_SMEM_BYTES ((WROW*128*3 + WROW*20)*4 + 512*4 + 64)

__global__ __launch_bounds__(128, 1) void scan_kernel(
    const float* __restrict__ xin,
    const float* __restrict__ mask,
    const float* __restrict__ w_h1h1, const float* __restrict__ b_h1h1,
    const float* __restrict__ w_h1h2, const float* __restrict__ b_h1h2,
    const float* __restrict__ w_h2h2, const float* __restrict__ b_h2h2,
    const float* __restrict__ w_h2o,  const float* __restrict__ b_h2o,
    const float* __restrict__ tau_adp_h1, const float* __restrict__ tau_adp_h2,
    const float* __restrict__ tau_m_h1,   const float* __restrict__ tau_m_h2,
    const float* __restrict__ tau_m_o,
    const float* __restrict__ hid1_mem0,  const float* __restrict__ hid2_mem0,
    const float* __restrict__ out_mem0,
    float* __restrict__ om_out,
    float* __restrict__ out)
{
    extern __shared__ unsigned char smraw[];
    float* w11s = (float*)smraw;                 // 129*128 (masked, zero pad row)
    float* w12s = w11s + WROW * 128;             // 129*128
    float* w22s = w12s + WROW * 128;             // 129*128
    float* w2os = w22s + WROW * 128;             // 129*20
    int*   list1 = (int*)(w2os + WROW * 20);     // [2][128]
    int*   list2 = list1 + 256;                  // [2][128]
    unsigned* m1s = (unsigned*)(list2 + 256);    // [2][4]  (E0,O0,E1,O1)
    unsigned* m2s = m1s + 8;                     // [2][4]

    const int tid  = threadIdx.x;
    const int r    = tid >> 6;        // row within CTA
    const int l    = tid & 63;        // h-pair index
    const int wrow = l >> 5;          // warp within row (0,1)
    const int lane = tid & 31;
    const int grow = blockIdx.x * 2 + r;
    const int barid = 1 + r;
    const int h0 = 2 * l;             // even h of this thread

    // ---- load weights (masked) + zero pad rows ----
    for (int i = tid; i < 16384; i += 128) {
        w11s[i] = __fmul_rn(w_h1h1[i], mask[i]);
        w12s[i] = w_h1h2[i];
        w22s[i] = __fmul_rn(w_h2h2[i], mask[16384 + i]);
    }
    for (int i = tid; i < 2560; i += 128) w2os[i] = w_h2o[i];
    if (tid < 128) {
        w11s[16384 + tid] = 0.f;
        w12s[16384 + tid] = 0.f;
        w22s[16384 + tid] = 0.f;
    }
    if (tid < 20) w2os[2560 + tid] = 0.f;

    // ---- per-thread parameters & state (2 h each) ----
    float a1[2], r1[2], a2[2], r2[2], oma1[2], omr1[2], oma2[2], omr2[2];
    float b11r[2], b12a[2], b12b[2];
    float h1m[2], h2m[2], b1[2], b2[2], h1sp[2], h2sp[2], s1c[2], s2c[2];
#pragma unroll
    for (int j = 0; j < 2; j++) {
        int h = h0 + j;
        a1[j] = decay(tau_m_h1[h]);
        r1[j] = decay(tau_adp_h1[h]);
        a2[j] = decay(tau_m_h2[h]);
        r2[j] = decay(tau_adp_h2[h]);
        oma1[j] = __fsub_rn(1.0f, a1[j]);
        omr1[j] = __fsub_rn(1.0f, r1[j]);
        oma2[j] = __fsub_rn(1.0f, a2[j]);
        omr2[j] = __fsub_rn(1.0f, r2[j]);
        b11r[j] = b_h1h1[h];
        b12a[j] = b_h1h2[h];
        b12b[j] = b_h2h2[h];
        h1m[j] = hid1_mem0[grow * HH + h];
        h2m[j] = hid2_mem0[grow * HH + h];
        b1[j] = B_J0; b2[j] = B_J0;
        h1sp[j] = 0.f; h2sp[j] = 0.f;
        s1c[j] = 0.f; s2c[j] = 0.f;
    }
    ull d11 = 0ull, d22 = 0ull;     // hoisted gather pairs

    // readout: threads l<10 own output column pair (2l, 2l+1)
    const bool ro = (l < 10);
    const int eo = ro ? h0 : 0;     // w2o column offset (dummy for l>=10)
    float om[2] = {0.f, 0.f}, aoo[2] = {0.f, 0.f}, omao[2] = {0.f, 0.f}, bo[2] = {0.f, 0.f};
    if (ro) {
#pragma unroll
        for (int j = 0; j < 2; j++) {
            om[j]   = out_mem0[grow * OO + h0 + j];
            aoo[j]  = decay(tau_m_o[h0 + j]);
            omao[j] = __fsub_rn(1.0f, aoo[j]);
            bo[j]   = b_h2o[h0 + j];
        }
    }
    __syncthreads();

    float2 xt = *(const float2*)&xin[((size_t)0 * BT + grow) * HH + h0];
    int c1p = 0, c2p = 0;

    for (int t = 0; t < TT; t++) {
        float2 xnext = make_float2(0.f, 0.f);
        if (t + 1 < TT)
            xnext = __ldg((const float2*)&xin[((size_t)(t + 1) * BT + grow) * HH + h0]);

        // ---- layer 1 (d11 hoisted) ----
        float2 d11f = unpack2(d11);
        float d11a[2] = {d11f.x, d11f.y};
        float xta[2] = {xt.x, xt.y};
        float sp1[2];
#pragma unroll
        for (int j = 0; j < 2; j++) {
            float i1 = __fadd_rn(__fadd_rn(xta[j], d11a[j]), b11r[j]);
            b1[j] = __fadd_rn(__fmul_rn(r1[j], b1[j]), __fmul_rn(omr1[j], h1sp[j]));
            float B1 = __fadd_rn(B_J0, __fmul_rn(BETA, b1[j]));
            h1m[j] = __fsub_rn(__fadd_rn(__fmul_rn(h1m[j], a1[j]), __fmul_rn(oma1[j], i1)),
                               __fmul_rn(B1, h1sp[j]));
            sp1[j] = (__fsub_rn(h1m[j], B1) > 0.0f) ? 1.0f : 0.0f;
            s1c[j] += sp1[j];
        }

        unsigned E = __ballot_sync(0xffffffffu, sp1[0] != 0.0f);
        unsigned Od = __ballot_sync(0xffffffffu, sp1[1] != 0.0f);
        if (lane == 0) { m1s[r * 4 + wrow * 2] = E; m1s[r * 4 + wrow * 2 + 1] = Od; }
        asm volatile("bar.sync %0, 64;" :: "r"(barid) : "memory");   // B1

        unsigned E0 = m1s[r * 4 + 0], O0 = m1s[r * 4 + 1];
        unsigned E1 = m1s[r * 4 + 2], O1 = m1s[r * 4 + 3];
        int c1 = __popc(E0) + __popc(O0) + __popc(E1) + __popc(O1);
        int c1np = (c1 + 3) & ~3;
        {
            int* Lr = list1 + (r << 7);
            int base = wrow ? (__popc(E0) + __popc(O0)) : 0;
            unsigned below = (1u << lane) - 1u;
            int rk = base + __popc(E & below) + __popc(Od & below);
            if (sp1[0] != 0.0f) Lr[rk] = h0;
            if (sp1[1] != 0.0f) Lr[rk + (int)((E >> lane) & 1u)] = h0 + 1;
            if (l >= c1 && l < c1np) Lr[l] = 128;
            if (l + 64 >= c1 && l + 64 < c1np) Lr[l + 64] = 128;
        }
        asm volatile("bar.sync %0, 64;" :: "r"(barid) : "memory");   // B2

        // ---- dual gather: d12(t) and d11(t+1) over list1 ----
        ull d12p, d11n;
        dual_gather2<128>(w12s, w11s, list1 + (r << 7), c1np, h0, h0, d12p, d11n);

        // ---- layer 2 (d22 hoisted) ----
        float2 d12f = unpack2(d12p);
        float2 d22f = unpack2(d22);
        float d12a[2] = {d12f.x, d12f.y};
        float d22a[2] = {d22f.x, d22f.y};
        float sp2[2];
#pragma unroll
        for (int j = 0; j < 2; j++) {
            float i2 = __fadd_rn(__fadd_rn(__fadd_rn(d12a[j], b12a[j]), d22a[j]), b12b[j]);
            b2[j] = __fadd_rn(__fmul_rn(r2[j], b2[j]), __fmul_rn(omr2[j], h2sp[j]));
            float B2 = __fadd_rn(B_J0, __fmul_rn(BETA, b2[j]));
            h2m[j] = __fsub_rn(__fadd_rn(__fmul_rn(h2m[j], a2[j]), __fmul_rn(oma2[j], i2)),
                               __fmul_rn(B2, h2sp[j]));
            sp2[j] = (__fsub_rn(h2m[j], B2) > 0.0f) ? 1.0f : 0.0f;
            s2c[j] += sp2[j];
        }

        unsigned F = __ballot_sync(0xffffffffu, sp2[0] != 0.0f);
        unsigned P = __ballot_sync(0xffffffffu, sp2[1] != 0.0f);
        if (lane == 0) { m2s[r * 4 + wrow * 2] = F; m2s[r * 4 + wrow * 2 + 1] = P; }
        asm volatile("bar.sync %0, 64;" :: "r"(barid) : "memory");   // B3

        unsigned F0 = m2s[r * 4 + 0], P0 = m2s[r * 4 + 1];
        unsigned F1 = m2s[r * 4 + 2], P1 = m2s[r * 4 + 3];
        int c2 = __popc(F0) + __popc(P0) + __popc(F1) + __popc(P1);
        int c2np = (c2 + 3) & ~3;
        {
            int* Lr = list2 + (r << 7);
            int base = wrow ? (__popc(F0) + __popc(P0)) : 0;
            unsigned below = (1u << lane) - 1u;
            int rk = base + __popc(F & below) + __popc(P & below);
            if (sp2[0] != 0.0f) Lr[rk] = h0;
            if (sp2[1] != 0.0f) Lr[rk + (int)((F >> lane) & 1u)] = h0 + 1;
            if (l >= c2 && l < c2np) Lr[l] = 128;
            if (l + 64 >= c2 && l + 64 < c2np) Lr[l + 64] = 128;
        }
        asm volatile("bar.sync %0, 64;" :: "r"(barid) : "memory");   // B4

        // ---- dual gather: d22(t+1) and d2o(t) over list2 ----
        ull d22n, d2op;
        dual_gather2<20>(w22s, w2os, list2 + (r << 7), c2np, h0, eo, d22n, d2op);

        // ---- readout om update (softmax deferred) ----
        if (ro) {
            float2 d2of = unpack2(d2op);
            float d2oa[2] = {d2of.x, d2of.y};
#pragma unroll
            for (int j = 0; j < 2; j++) {
                float io = __fadd_rn(d2oa[j], bo[j]);
                om[j] = __fadd_rn(__fmul_rn(om[j], aoo[j]), __fmul_rn(omao[j], io));
            }
            *(float2*)&om_out[((size_t)t * BT + grow) * OO + h0] = make_float2(om[0], om[1]);
        }

#pragma unroll
        for (int j = 0; j < 2; j++) { h1sp[j] = sp1[j]; h2sp[j] = sp2[j]; }
        d11 = d11n;
        d22 = d22n;
        c1p = c1np; c2p = c2np;
        xt = xnext;
    }

    *(float2*)&out[OUT_OFF_S1 + grow * HH + h0] =
        make_float2(__fdiv_rn(s1c[0], (float)TT), __fdiv_rn(s1c[1], (float)TT));
    *(float2*)&out[OUT_OFF_S2 + grow * HH + h0] =
        make_float2(__fdiv_rn(s2c[0], (float)TT), __fdiv_rn(s2c[1], (float)TT));
    (void)c1p; (void)c2p;
}

// ---------------------------------------------------------------------------
// Kernel 2b: softmax + ascending-t accumulation per batch row.
// ---------------------------------------------------------------------------
__global__ __launch_bounds__(256) void softmax_acc_kernel(
    const float* __restrict__ om_in, float* __restrict__ out)
{
    __shared__ float sm[(TT - 11) * OO];
    const int b = blockIdx.x;
    const int wid = threadIdx.x >> 5;
    const int lane = threadIdx.x & 31;

    for (int t = 11 + wid; t < TT; t += 8) {
        float om = (lane < OO) ? om_in[((size_t)t * BT + b) * OO + lane] : 0.f;
        float v = (lane < OO) ? om : -3.4e38f;
#pragma unroll
        for (int d = 16; d; d >>= 1) v = fmaxf(v, __shfl_xor_sync(0xffffffffu, v, d));
        float e = (lane < OO) ? expf(__fsub_rn(om, v)) : 0.f;
        float ssum = e;
#pragma unroll
        for (int d = 16; d; d >>= 1) ssum += __shfl_xor_sync(0xffffffffu, ssum, d);
        if (lane < OO) sm[(t - 11) * OO + lane] = __fdiv_rn(e, ssum);
    }
    __syncthreads();

    if (threadIdx.x < OO) {
        float a = 0.f;
        for (int tt = 0; tt < TT - 11; tt++)
            a = __fadd_rn(a, sm[tt * OO + threadIdx.x]);
        out[OUT_OFF_ACC + b * OO + threadIdx.x] = a;
    }
}

// ---------------------------------------------------------------------------
// Kernel 3a/3b: A_norm (deterministic two-pass)
// ---------------------------------------------------------------------------
__global__ __launch_bounds__(256) void norm_part_kernel(
    const float* __restrict__ w11, const float* __restrict__ w22,
    const float* __restrict__ mask)
{
    __shared__ float red[256];
    int i = blockIdx.x * 256 + threadIdx.x;
    float s = fabsf(__fmul_rn(w11[i], mask[i]))
            + fabsf(__fmul_rn(w22[i], mask[16384 + i]));
    red[threadIdx.x] = s;
    __syncthreads();
    for (int d = 128; d > 0; d >>= 1) {
        if (threadIdx.x < d) red[threadIdx.x] += red[threadIdx.x + d];
        __syncthreads();
    }
    if (threadIdx.x == 0) g_npart[blockIdx.x] = red[0];
}

__global__ void norm_finish_kernel(float* __restrict__ out)
{
    int lane = threadIdx.x;
    __shared__ float w[2];
    float s = g_npart[lane];
#pragma unroll
    for (int d = 16; d; d >>= 1) s += __shfl_xor_sync(0xffffffffu, s, d);
    if ((lane & 31) == 0) w[lane >> 5] = s;
    __syncthreads();
    if (lane == 0) out[OUT_OFF_NORM] = w[0] + w[1];
}

// ---------------------------------------------------------------------------
extern "C" void kernel_launch(void* const* d_in, const int* in_sizes, int n_in,
                              void* d_out, int out_size)
{
    const float* x          = (const float*)d_in[0];
    const float* mask       = (const float*)d_in[1];
    const float* w_ih1      = (const float*)d_in[2];
    const float* b_ih1      = (const float*)d_in[3];
    const float* w_h1h1     = (const float*)d_in[4];
    const float* b_h1h1     = (const float*)d_in[5];
    const float* w_h1h2     = (const float*)d_in[6];
    const float* b_h1h2     = (const float*)d_in[7];
    const float* w_h2h2     = (const float*)d_in[8];
    const float* b_h2h2     = (const float*)d_in[9];
    const float* w_h2o      = (const float*)d_in[10];
    const float* b_h2o      = (const float*)d_in[11];
    const float* tau_adp_h1 = (const float*)d_in[12];
    const float* tau_adp_h2 = (const float*)d_in[13];
    const float* tau_m_h1   = (const float*)d_in[14];
    const float* tau_m_h2   = (const float*)d_in[15];
    const float* tau_m_o    = (const float*)d_in[16];
    const float* hid1_mem0  = (const float*)d_in[17];
    const float* hid2_mem0  = (const float*)d_in[18];
    const float* out_mem0   = (const float*)d_in[19];
    float* out = (float*)d_out;

    float* xin = nullptr;
    cudaGetSymbolAddress((void**)&xin, g_xin);
    float* omb = nullptr;
    cudaGetSymbolAddress((void**)&omb, g_om);

    cudaFuncSetAttribute(scan_kernel, cudaFuncAttributeMaxDynamicSharedMemorySize,
                         SCAN_SMEM_BYTES);

    gemm_xin_kernel<<<(BT * TT) / GTM, 256>>>(x, w_ih1, b_ih1, xin);
    scan_kernel<<<BT / 2, 128, SCAN_SMEM_BYTES>>>(
        xin, mask, w_h1h1, b_h1h1, w_h1h2, b_h1h2, w_h2h2, b_h2h2,
        w_h2o, b_h2o, tau_adp_h1, tau_adp_h2, tau_m_h1, tau_m_h2, tau_m_o,
        hid1_mem0, hid2_mem0, out_mem0, omb, out);
    softmax_acc_kernel<<<BT, 256>>>(omb, out);
    norm_part_kernel<<<64, 256>>>(w_h1h1, w_h2h2, mask);
    norm_finish_kernel<<<1, 64>>>(out);
}